// round 7
// baseline (speedup 1.0000x reference)
#include <cuda_runtime.h>

// Problem constants
#define B   128
#define S   37
#define T   2048
#define D   256
#define STC 8
#define C   2
#define MERGED 264     // D + STC
#define F2  74         // 2*S features
#define NT  256        // threads per block (reduce)
#define G   (T/4)      // 512 float4 groups along time
#define PB  8          // time partitions per batch
#define GP  (G/PB)     // 64 float4 groups per partition

// Head config: one CTA owns BT2 batches and ALL 264 j-columns.
#define NT2 288        // 9 warps; thread = j column (264 active)
#define BT2 4
#define NB2 (B/BT2)    // 32 CTAs

// Scratch (device global; every slot written by exactly one CTA -> deterministic)
__device__ float g_part[B][PB][F2 + 2];    // reduce partials

__device__ __forceinline__ float warp_sum(float v) {
#pragma unroll
    for (int o = 16; o; o >>= 1) v += __shfl_xor_sync(0xffffffffu, v, o);
    return v;
}

// ---------------------------------------------------------------------------
// Kernel 1: streaming reduction over time.  grid = B*PB, block = 256.
// Warp w owns sensors {w, w+8, ...} (<=5), lanes stride the 64 time-groups.
// ---------------------------------------------------------------------------
__global__ __launch_bounds__(NT, 3)
void reduce_kernel(const float* __restrict__ x,
                   const float* __restrict__ time_in,
                   const int*   __restrict__ smask)
{
    __shared__ unsigned vmask[GP];   // per-group 4-bit validity (1 bit per t)
    __shared__ float feat_s[F2];
    __shared__ float ssum_s[4];      // [0..1] tsum per warp, [2..3] denom per warp

    const int bp   = blockIdx.x;
    const int b    = bp >> 3;
    const int p    = bp & (PB - 1);
    const int tid  = threadIdx.x;
    const int lane = tid & 31;
    const int wid  = tid >> 5;

    if (tid < GP) vmask[tid] = 0u;
    __syncthreads();

    const float4* __restrict__ x4 = (const float4*)x     + (size_t)b * S * G;
    const int4*   __restrict__ m4 = (const int4*)smask   + (size_t)b * S * G;
    const int gbase = p * GP;

    float accx[5] = {0.f, 0.f, 0.f, 0.f, 0.f};
    float accm[5] = {0.f, 0.f, 0.f, 0.f, 0.f};
    const int ns = (wid < 5) ? 5 : 4;     // sensors this warp owns (37 = 5*5 + 3*4)

#pragma unroll
    for (int gi = 0; gi < GP / 32; gi++) {
        const int g = gbase + lane + gi * 32;
        unsigned bits = 0u;
#pragma unroll
        for (int i = 0; i < 5; i++) {
            if (i < ns) {                  // warp-uniform
                const int s = wid + 8 * i;
                const int idx = s * G + g;
                float4 xv = x4[idx];
                int4   mv = m4[idx];
                // Feature sums need no mask: invalid timestep => all features 0.
                accx[i] += (xv.x + xv.y) + (xv.z + xv.w);
                accm[i] += (float)((mv.x + mv.y) + (mv.z + mv.w));
                bits |= (xv.x != 0.f || mv.x != 0) ? 1u : 0u;
                bits |= (xv.y != 0.f || mv.y != 0) ? 2u : 0u;
                bits |= (xv.z != 0.f || mv.z != 0) ? 4u : 0u;
                bits |= (xv.w != 0.f || mv.w != 0) ? 8u : 0u;
            }
        }
        if (bits) atomicOr(&vmask[g - gbase], bits);
    }

    // per-sensor warp reduction; each sensor owned by exactly one warp
#pragma unroll
    for (int i = 0; i < 5; i++) {
        if (i < ns) {
            float vx = warp_sum(accx[i]);
            float vm = warp_sum(accm[i]);
            if (lane == 0) {
                const int s = wid + 8 * i;
                feat_s[s]     = vx;
                feat_s[S + s] = vm;
            }
        }
    }
    __syncthreads();

    // denom & masked time-sum from the assembled validity bitmask
    float dcnt = 0.f, tsum = 0.f;
    if (tid < GP) {
        const unsigned bits = vmask[tid];
        float4 tv = ((const float4*)time_in)[b * G + gbase + tid];
        dcnt = (float)__popc(bits & 0xFu);
        tsum = (bits & 1u ? tv.x : 0.f) + (bits & 2u ? tv.y : 0.f)
             + (bits & 4u ? tv.z : 0.f) + (bits & 8u ? tv.w : 0.f);
    }
    if (wid < 2) {
        float t = warp_sum(tsum);
        float d = warp_sum(dcnt);
        if (lane == 0) { ssum_s[wid] = t; ssum_s[2 + wid] = d; }
    }
    __syncthreads();

    float* __restrict__ dst = &g_part[b][p][0];
    if (tid < F2)           dst[tid]    = feat_s[tid];
    else if (tid == F2)     dst[F2]     = ssum_s[0] + ssum_s[1];
    else if (tid == F2 + 1) dst[F2 + 1] = ssum_s[2] + ssum_s[3];
}

// ---------------------------------------------------------------------------
// Kernel 2: fused head.  grid = 32 CTAs (4 batches each), block = 288.
// Phase 1: fold g_part partials.  Phase 2: pooled + static embedding (smem).
// Phase 3: merge GEMM (thread = j column, 4 batch accumulators) + ReLU +
//          classifier, reduced entirely inside the CTA.  Outputs written here.
// ---------------------------------------------------------------------------
__global__ __launch_bounds__(NT2, 1)
void head_kernel(const float* __restrict__ static_in,
                 const float* __restrict__ W_sensor,  // [74,256]
                 const float* __restrict__ b_sensor,  // [256]
                 const float* __restrict__ W_time,    // [1,256]
                 const float* __restrict__ b_time,    // [256]
                 const float* __restrict__ W_static,  // [8,8]
                 const float* __restrict__ b_static,  // [8]
                 const float* __restrict__ W_merge,   // [264,264]
                 const float* __restrict__ b_merge,   // [264]
                 const float* __restrict__ W_cls,     // [264,2]
                 const float* __restrict__ b_cls,     // [2]
                 float* __restrict__ out)             // [B,2]
{
    __shared__ float sfeat[BT2][F2 + 2];
    __shared__ float sscal[BT2][3];            // inv, r, ts per batch
    __shared__ float scomb[BT2][MERGED];
    __shared__ float spart[NT2 / 32][BT2][2];  // per-warp classifier partials

    const int b0   = blockIdx.x * BT2;
    const int tid  = threadIdx.x;
    const int lane = tid & 31;
    const int wid  = tid >> 5;

    // ---- Phase 1: fold reduce partials ----
    for (int i = tid; i < BT2 * (F2 + 2); i += NT2) {
        const int bb = i / (F2 + 2), f = i % (F2 + 2);
        float v = 0.f;
#pragma unroll
        for (int p = 0; p < PB; p++) v += g_part[b0 + bb][p][f];
        sfeat[bb][f] = v;
    }
    __syncthreads();

    if (tid < BT2) {
        const float dn  = sfeat[tid][F2 + 1];
        const float inv = 1.f / fmaxf(dn, 1e-9f);
        sscal[tid][0] = inv;
        sscal[tid][1] = dn * inv;              // 1.0 normally, 0.0 if empty
        sscal[tid][2] = sfeat[tid][F2] * inv;  // masked mean time
    }
    __syncthreads();

    // ---- Phase 2: embedding ----
    if (tid < D) {
        // thread = channel d; one coalesced W_sensor load feeds 4 batches
        float acc[BT2] = {0.f, 0.f, 0.f, 0.f};
#pragma unroll
        for (int f = 0; f < F2; f++) {
            const float w = W_sensor[f * D + tid];
#pragma unroll
            for (int bb = 0; bb < BT2; bb++)
                acc[bb] = fmaf(sfeat[bb][f], w, acc[bb]);
        }
        const float bs = b_sensor[tid] + b_time[tid];
        const float wt = W_time[tid];
#pragma unroll
        for (int bb = 0; bb < BT2; bb++)
            scomb[bb][tid] = acc[bb] * sscal[bb][0]
                           + sscal[bb][1] * bs
                           + sscal[bb][2] * wt;
    } else {
        // warp 8 (threads 256..287): static embedding, 4 batches x 8 channels
        const int t2 = tid - D;                // 0..31
        const int bb = t2 >> 3, c = t2 & 7;
        float acc = b_static[c];
#pragma unroll
        for (int k = 0; k < STC; k++)
            acc = fmaf(static_in[(b0 + bb) * STC + k], W_static[k * STC + c], acc);
        scomb[bb][D + c] = acc;
    }
    __syncthreads();

    // ---- Phase 3: merge GEMM + ReLU + classifier ----
    const bool  valid = (tid < MERGED);
    const int   jc    = valid ? tid : (MERGED - 1);
    float acc[BT2];
    {
        const float bm = b_merge[jc];
#pragma unroll
        for (int bb = 0; bb < BT2; bb++) acc[bb] = bm;
    }
#pragma unroll 8
    for (int k = 0; k < MERGED; k++) {
        const float w = W_merge[k * MERGED + jc];
#pragma unroll
        for (int bb = 0; bb < BT2; bb++)
            acc[bb] = fmaf(scomb[bb][k], w, acc[bb]);
    }

    const float w0 = W_cls[jc * C + 0];
    const float w1 = W_cls[jc * C + 1];
#pragma unroll
    for (int bb = 0; bb < BT2; bb++) {
        const float h  = valid ? fmaxf(acc[bb], 0.f) : 0.f;
        const float p0 = warp_sum(h * w0);
        const float p1 = warp_sum(h * w1);
        if (lane == 0) { spart[wid][bb][0] = p0; spart[wid][bb][1] = p1; }
    }
    __syncthreads();

    if (tid < BT2 * C) {
        const int bb = tid >> 1, c = tid & 1;
        float v = b_cls[c];
#pragma unroll
        for (int w = 0; w < NT2 / 32; w++) v += spart[w][bb][c];
        out[(b0 + bb) * C + c] = v;
    }
}

extern "C" void kernel_launch(void* const* d_in, const int* in_sizes, int n_in,
                              void* d_out, int out_size)
{
    const float* x        = (const float*)d_in[0];
    const float* stat     = (const float*)d_in[1];
    const float* time_in  = (const float*)d_in[2];
    const int*   smask    = (const int*)  d_in[3];
    const float* W_sensor = (const float*)d_in[4];
    const float* b_sensor = (const float*)d_in[5];
    const float* W_time   = (const float*)d_in[6];
    const float* b_time   = (const float*)d_in[7];
    const float* W_static = (const float*)d_in[8];
    const float* b_static = (const float*)d_in[9];
    const float* W_merge  = (const float*)d_in[10];
    const float* b_merge  = (const float*)d_in[11];
    const float* W_cls    = (const float*)d_in[12];
    const float* b_cls    = (const float*)d_in[13];
    float* out = (float*)d_out;

    reduce_kernel<<<B * PB, NT>>>(x, time_in, smask);
    head_kernel<<<NB2, NT2>>>(stat, W_sensor, b_sensor, W_time, b_time,
                              W_static, b_static, W_merge, b_merge,
                              W_cls, b_cls, out);
}

// round 8
// speedup vs baseline: 1.0156x; 1.0156x over previous
#include <cuda_runtime.h>

// Problem constants
#define B   128
#define S   37
#define T   2048
#define D   256
#define STC 8
#define C   2
#define MERGED 264     // D + STC
#define F2  74         // 2*S features
#define NT  256        // threads per block
#define G   (T/4)      // 512 float4 groups along time
#define PB  4          // time partitions per batch (grid 512 = single wave @ occ 4)
#define GP  (G/PB)     // 128 float4 groups per partition

// Head tiling
#define BT      8                   // batches per head CTA (= warps)
#define BTILES  (B/BT)              // 16
#define JT      32                  // j columns per head CTA (= lanes)
#define JTILES  ((MERGED+JT-1)/JT)  // 9 (last tile ragged)

// Scratch (device globals; every slot written by exactly one CTA -> deterministic)
__device__ float g_part[B][PB][F2 + 2];    // reduce partials
__device__ float g_partC[B][JTILES][2];    // classifier partials per j-tile

__device__ __forceinline__ float warp_sum(float v) {
#pragma unroll
    for (int o = 16; o; o >>= 1) v += __shfl_xor_sync(0xffffffffu, v, o);
    return v;
}

// ---------------------------------------------------------------------------
// Kernel 1: streaming reduction over time.  grid = B*PB = 512, block = 256.
// Warp w owns sensors {w, w+8, ...} (<=5), lanes stride the 128 time-groups.
// ---------------------------------------------------------------------------
__global__ __launch_bounds__(NT, 4)
void reduce_kernel(const float* __restrict__ x,
                   const float* __restrict__ time_in,
                   const int*   __restrict__ smask)
{
    __shared__ unsigned vmask[GP];   // per-group 4-bit validity (1 bit per t)
    __shared__ float feat_s[F2];
    __shared__ float ssum_s[8];      // [0..3] tsum per warp, [4..7] denom per warp

    const int bp   = blockIdx.x;
    const int b    = bp >> 2;            // PB = 4
    const int p    = bp & (PB - 1);
    const int tid  = threadIdx.x;
    const int lane = tid & 31;
    const int wid  = tid >> 5;

    if (tid < GP) vmask[tid] = 0u;
    __syncthreads();

    const float4* __restrict__ x4 = (const float4*)x     + (size_t)b * S * G;
    const int4*   __restrict__ m4 = (const int4*)smask   + (size_t)b * S * G;
    const int gbase = p * GP;

    float accx[5] = {0.f, 0.f, 0.f, 0.f, 0.f};
    float accm[5] = {0.f, 0.f, 0.f, 0.f, 0.f};
    const int ns = (wid < 5) ? 5 : 4;     // sensors this warp owns (37 = 5*5 + 3*4)

#pragma unroll
    for (int gi = 0; gi < GP / 32; gi++) {
        const int g = gbase + lane + gi * 32;
        unsigned bits = 0u;
#pragma unroll
        for (int i = 0; i < 5; i++) {
            if (i < ns) {                  // warp-uniform
                const int s = wid + 8 * i;
                const int idx = s * G + g;
                float4 xv = x4[idx];
                int4   mv = m4[idx];
                // Feature sums need no mask: invalid timestep => all features 0.
                accx[i] += (xv.x + xv.y) + (xv.z + xv.w);
                accm[i] += (float)((mv.x + mv.y) + (mv.z + mv.w));
                bits |= (xv.x != 0.f || mv.x != 0) ? 1u : 0u;
                bits |= (xv.y != 0.f || mv.y != 0) ? 2u : 0u;
                bits |= (xv.z != 0.f || mv.z != 0) ? 4u : 0u;
                bits |= (xv.w != 0.f || mv.w != 0) ? 8u : 0u;
            }
        }
        if (bits) atomicOr(&vmask[g - gbase], bits);
    }

    // per-sensor warp reduction; each sensor owned by exactly one warp
#pragma unroll
    for (int i = 0; i < 5; i++) {
        if (i < ns) {
            float vx = warp_sum(accx[i]);
            float vm = warp_sum(accm[i]);
            if (lane == 0) {
                const int s = wid + 8 * i;
                feat_s[s]     = vx;
                feat_s[S + s] = vm;
            }
        }
    }
    __syncthreads();

    // denom & masked time-sum from the assembled validity bitmask (4 warps)
    float dcnt = 0.f, tsum = 0.f;
    if (tid < GP) {
        const unsigned bits = vmask[tid];
        float4 tv = ((const float4*)time_in)[b * G + gbase + tid];
        dcnt = (float)__popc(bits & 0xFu);
        tsum = (bits & 1u ? tv.x : 0.f) + (bits & 2u ? tv.y : 0.f)
             + (bits & 4u ? tv.z : 0.f) + (bits & 8u ? tv.w : 0.f);
    }
    if (wid < 4) {
        float t = warp_sum(tsum);
        float d = warp_sum(dcnt);
        if (lane == 0) { ssum_s[wid] = t; ssum_s[4 + wid] = d; }
    }
    __syncthreads();

    float* __restrict__ dst = &g_part[b][p][0];
    if (tid < F2) {
        dst[tid] = feat_s[tid];
    } else if (tid == F2) {
        dst[F2] = (ssum_s[0] + ssum_s[1]) + (ssum_s[2] + ssum_s[3]);
    } else if (tid == F2 + 1) {
        dst[F2 + 1] = (ssum_s[4] + ssum_s[5]) + (ssum_s[6] + ssum_s[7]);
    }
}

// ---------------------------------------------------------------------------
// Kernel 2: fused embed + merge GEMM + classifier partials.
// grid = (JTILES, BTILES) = (9,16) = 144 CTAs (~1/SM), block = 256.
// Each CTA: folds g_part for its 8 batches, computes their embedding into
// smem, stages its W_merge column slice, then warp = batch / lane = j-col.
// ---------------------------------------------------------------------------
__global__ __launch_bounds__(NT, 1)
void head_kernel(const float* __restrict__ static_in,
                 const float* __restrict__ W_sensor,  // [74,256]
                 const float* __restrict__ b_sensor,  // [256]
                 const float* __restrict__ W_time,    // [1,256]
                 const float* __restrict__ b_time,    // [256]
                 const float* __restrict__ W_static,  // [8,8]
                 const float* __restrict__ b_static,  // [8]
                 const float* __restrict__ W_merge,   // [264,264]
                 const float* __restrict__ b_merge,   // [264]
                 const float* __restrict__ W_cls)     // [264,2]
{
    __shared__ float sfeat[BT][F2 + 2];   // 2.5 KB
    __shared__ float sscal[BT][3];        // inv, r, ts
    __shared__ float scomb[BT][MERGED];   // 8.4 KB
    __shared__ float sw[MERGED * JT];     // 33.8 KB, [k][jx] lane-banked

    const int jt   = blockIdx.x;
    const int b0   = blockIdx.y * BT;
    const int j0   = jt * JT;
    const int tid  = threadIdx.x;
    const int lane = tid & 31;
    const int wid  = tid >> 5;

    // ---- stage W_merge column slice (overlaps with fold/embed loads) ----
    const int jcol  = j0 + lane;
    const int jcolc = (jcol < MERGED) ? jcol : (MERGED - 1);
#pragma unroll 4
    for (int kk = wid; kk < MERGED; kk += 8)
        sw[kk * JT + lane] = W_merge[kk * MERGED + jcolc];

    // ---- fold reduce partials for this CTA's 8 batches ----
    for (int i = tid; i < BT * (F2 + 2); i += NT) {
        const int bb = i / (F2 + 2), f = i % (F2 + 2);
        float v = 0.f;
#pragma unroll
        for (int p = 0; p < PB; p++) v += g_part[b0 + bb][p][f];
        sfeat[bb][f] = v;
    }
    __syncthreads();

    if (tid < BT) {
        const float dn  = sfeat[tid][F2 + 1];
        const float inv = 1.f / fmaxf(dn, 1e-9f);
        sscal[tid][0] = inv;
        sscal[tid][1] = dn * inv;              // 1.0 normally, 0.0 if empty
        sscal[tid][2] = sfeat[tid][F2] * inv;  // masked mean time
    }
    __syncthreads();

    // ---- embedding: thread = channel d, 8 batch accumulators ----
    {
        float acc[BT];
#pragma unroll
        for (int bb = 0; bb < BT; bb++) acc[bb] = 0.f;
#pragma unroll 2
        for (int f = 0; f < F2; f++) {
            const float w = W_sensor[f * D + tid];
#pragma unroll
            for (int bb = 0; bb < BT; bb++)
                acc[bb] = fmaf(sfeat[bb][f], w, acc[bb]);
        }
        const float bs = b_sensor[tid] + b_time[tid];
        const float wt = W_time[tid];
#pragma unroll
        for (int bb = 0; bb < BT; bb++)
            scomb[bb][tid] = acc[bb] * sscal[bb][0]
                           + sscal[bb][1] * bs
                           + sscal[bb][2] * wt;
    }
    if (tid < BT * STC) {     // threads 0..63: static embedding
        const int bb = tid >> 3, c = tid & 7;
        float acc = b_static[c];
#pragma unroll
        for (int k = 0; k < STC; k++)
            acc = fmaf(static_in[(b0 + bb) * STC + k], W_static[k * STC + c], acc);
        scomb[bb][D + c] = acc;
    }
    __syncthreads();

    // ---- merge GEMM: warp = batch, lane = j column in tile ----
    float acc = b_merge[jcolc];
    const float* __restrict__ scb = &scomb[wid][0];
#pragma unroll 8
    for (int k = 0; k < MERGED; k++)
        acc = fmaf(scb[k], sw[k * JT + lane], acc);

    const float rlu = (jcol < MERGED) ? fmaxf(acc, 0.f) : 0.f;
    const float p0 = warp_sum(rlu * W_cls[jcolc * C + 0]);
    const float p1 = warp_sum(rlu * W_cls[jcolc * C + 1]);
    if (lane == 0) {
        g_partC[b0 + wid][jt][0] = p0;
        g_partC[b0 + wid][jt][1] = p1;
    }
}

// ---------------------------------------------------------------------------
// Kernel 3: final tiny reduction over j-tiles.  grid = 1, block = 256.
// ---------------------------------------------------------------------------
__global__ __launch_bounds__(NT, 1)
void final_kernel(const float* __restrict__ b_cls,
                  float* __restrict__ out)
{
    const int tid = threadIdx.x;     // B*C = 256 exactly
    const int b = tid >> 1, c = tid & 1;
    const float* __restrict__ pc = &g_partC[b][0][0];
    float v = b_cls[c];
#pragma unroll
    for (int jt = 0; jt < JTILES; jt++) v += pc[jt * 2 + c];
    out[tid] = v;
}

extern "C" void kernel_launch(void* const* d_in, const int* in_sizes, int n_in,
                              void* d_out, int out_size)
{
    const float* x        = (const float*)d_in[0];
    const float* stat     = (const float*)d_in[1];
    const float* time_in  = (const float*)d_in[2];
    const int*   smask    = (const int*)  d_in[3];
    const float* W_sensor = (const float*)d_in[4];
    const float* b_sensor = (const float*)d_in[5];
    const float* W_time   = (const float*)d_in[6];
    const float* b_time   = (const float*)d_in[7];
    const float* W_static = (const float*)d_in[8];
    const float* b_static = (const float*)d_in[9];
    const float* W_merge  = (const float*)d_in[10];
    const float* b_merge  = (const float*)d_in[11];
    const float* W_cls    = (const float*)d_in[12];
    const float* b_cls    = (const float*)d_in[13];
    float* out = (float*)d_out;

    reduce_kernel<<<B * PB, NT>>>(x, time_in, smask);
    head_kernel<<<dim3(JTILES, BTILES), NT>>>(stat,
                                              W_sensor, b_sensor, W_time, b_time,
                                              W_static, b_static, W_merge, b_merge,
                                              W_cls);
    final_kernel<<<1, NT>>>(b_cls, out);
}